// round 16
// baseline (speedup 1.0000x reference)
#include <cuda_runtime.h>
#include <cuda_fp16.h>
#include <cstdint>

#define BATCH 4096
#define IDIM  256
#define ODIM  512
#define KDIM  512   // fused K = 2 * IDIM

// Fragment-packed fp16 scratch:
//  g_actH: A fragments [mf(256)][kf16(32)][lane(32)] x uint4 (8 halfs)  = 4 MB
//  g_wpH : B fragments [kf16(32)][nf(64)][lane(32)] x uint2 (4 halfs)   = 0.5 MB
__device__ uint4 g_actH[256 * 32 * 32];
__device__ uint2 g_wpH[32 * 64 * 32];

__device__ __forceinline__ uint32_t h2_as_u32(__half2 h) {
    uint32_t u;
    *(__half2*)&u = h;
    return u;
}

__device__ __forceinline__ float fast_sigmoid_mul(float xv) {
    // xv * sigmoid(xv) with ex2/rcp approx (no slow IEEE div)
    float e;
    asm("ex2.approx.f32 %0, %1;" : "=f"(e) : "f"(-xv * 1.4426950408889634f));
    float r;
    asm("rcp.approx.f32 %0, %1;" : "=f"(r) : "f"(1.0f + e));
    return xv * r;
}

// ---------------------------------------------------------------------------
// Fused prep kernel.
//  blocks 0..31    : pack W = [wb; ws] into B fragments (staged via smem)
//  blocks 32..543  : activation -> A fragments. Block = (i-slice of 16 dims) x
//                    (128 batch rows). Per-interval cubic Horner table in smem:
//                    spline eval = 1 LDS.128 + 3 FMA. x pairs read as LDS.64.
// ---------------------------------------------------------------------------
#define WS_STR 520
#define XS_STR 18
#define WPACK_BLOCKS 32
#define ACT_BLOCKS   512
#define SBUF_FLOATS 8320   // max(wpack 16*520=8320, act 2304+1024+4096=7424)

__global__ __launch_bounds__(256) void kan_prep_kernel(
    const float* __restrict__ x, const float* __restrict__ cps,
    const float* __restrict__ wb, const float* __restrict__ ws) {
    __shared__ float sbuf[SBUF_FLOATS];
    const int tid = threadIdx.x;

    if (blockIdx.x < WPACK_BLOCKS) {
        // ---- W pack: one kf (16 k-rows) per block ----
        const int kf = blockIdx.x;
#pragma unroll
        for (int q = 0; q < 8; ++q) {
            int id = tid + 256 * q;            // 0..2047
            int krow = id >> 7, c4 = id & 127;
            int k = kf * 16 + krow;
            const float4* src = (const float4*)((k < 256 ? wb + (size_t)k * ODIM
                                                         : ws + (size_t)(k - 256) * ODIM));
            float4 v = src[c4];
            float* d = sbuf + krow * WS_STR + c4 * 4;
            d[0] = v.x; d[1] = v.y; d[2] = v.z; d[3] = v.w;
        }
        __syncthreads();
#pragma unroll
        for (int q = 0; q < 8; ++q) {
            int id   = tid + 256 * q;          // 0..2047 = nf*32 + lane
            int nf   = id >> 5;
            int lane = id & 31;
            int g = lane >> 2, t = lane & 3;
            int n = nf * 8 + g;
            uint2 o;
            o.x = h2_as_u32(__floats2half2_rn(sbuf[(2 * t)     * WS_STR + n],
                                              sbuf[(2 * t + 1) * WS_STR + n]));
            o.y = h2_as_u32(__floats2half2_rn(sbuf[(2 * t + 8) * WS_STR + n],
                                              sbuf[(2 * t + 9) * WS_STR + n]));
            g_wpH[((size_t)kf * 64 + nf) * 32 + lane] = o;
        }
    } else {
        // ---- Activation: 16 i-dims x 128 batch rows per block ----
        const int blk = blockIdx.x - WPACK_BLOCKS;
        const int ib  = blk & 15;     // i-slice: dims [ib*16, ib*16+16)
        const int bb  = blk >> 4;     // batch slice: rows [bb*128, bb*128+128)
        const int i0  = ib * 16;

        float*  xs  = sbuf;                       // [128][XS_STR]
        float*  cs  = sbuf + 128 * XS_STR;        // [16][64]
        float4* tab = (float4*)(sbuf + 128 * XS_STR + 1024);  // [16][64]

        // stage x tile: 128 rows x 16 dims (4 float4 per row)
#pragma unroll
        for (int q = 0; q < 2; ++q) {
            int id = tid + 256 * q;               // 0..511
            int r = id >> 2, c4 = id & 3;
            float4 v = *(const float4*)(x + (size_t)(bb * 128 + r) * IDIM + i0 + c4 * 4);
            float* d = xs + r * XS_STR + c4 * 4;
            d[0] = v.x; d[1] = v.y; d[2] = v.z; d[3] = v.w;
        }
        // stage cps slice: 16 rows x 64
        {
            int r = tid >> 4, c4 = tid & 15;
            float4 v = *(const float4*)(cps + (size_t)(i0 + r) * 64 + c4 * 4);
            float* d = cs + r * 64 + c4 * 4;
            d[0] = v.x; d[1] = v.y; d[2] = v.z; d[3] = v.w;
        }
        __syncthreads();

        // Horner table: spline on interval j of dim il is
        // p.x + t*(p.y + t*(p.z + t*p.w)), from cps[il, j-3..j] (zero outside 0..59)
#pragma unroll
        for (int q = 0; q < 4; ++q) {
            int e = tid + 256 * q;                // 0..1023
            if (e < 16 * 63) {
                int il = e / 63, j = e % 63;
                const float* c = cs + il * 64;
                int k0 = j - 3;
                float c0 = (k0     >= 0 && k0     < 60) ? c[k0]     : 0.0f;
                float c1 = (k0 + 1 >= 0 && k0 + 1 < 60) ? c[k0 + 1] : 0.0f;
                float c2 = (k0 + 2 >= 0 && k0 + 2 < 60) ? c[k0 + 2] : 0.0f;
                float c3 = (j < 60)                      ? c[j]      : 0.0f;
                const float s6 = 1.0f / 6.0f;
                float4 p;
                p.x = (c0 + 4.0f * c1 + c2) * s6;
                p.y = 3.0f * (c2 - c0) * s6;
                p.z = 3.0f * (c0 - 2.0f * c1 + c2) * s6;
                p.w = (-c0 + 3.0f * c1 - 3.0f * c2 + c3) * s6;
                tab[il * 64 + j] = p;
            }
        }
        __syncthreads();

        // emit fragments: 8 mf-locals x {silu, spline} x 32 lanes = 512 uint4
#pragma unroll
        for (int q = 0; q < 2; ++q) {
            int id   = tid + 256 * q;             // 0..511
            int mfl  = id >> 6;                   // 0..7
            int sel  = (id >> 5) & 1;             // warp-uniform: 0 silu, 1 spline
            int lane = id & 31;
            int g = lane >> 2, t = lane & 3;

            uint32_t hw[4];
#pragma unroll
            for (int hk = 0; hk < 2; ++hk) {
                int il = 2 * t + 8 * hk;
#pragma unroll
                for (int rr = 0; rr < 2; ++rr) {
                    int r = mfl * 16 + g + 8 * rr;
                    float2 xv2 = *(const float2*)(xs + r * XS_STR + il);  // 8B aligned
                    float res0, res1;
                    if (!sel) {
                        res0 = fast_sigmoid_mul(xv2.x);
                        res1 = fast_sigmoid_mul(xv2.y);
                    } else {
                        float u0 = (xv2.x + 1.0f) * 31.5f;
                        float u1 = (xv2.y + 1.0f) * 31.5f;
                        int j0 = (int)floorf(u0), j1 = (int)floorf(u1);
                        j0 = j0 < 0 ? 0 : (j0 > 62 ? 62 : j0);
                        j1 = j1 < 0 ? 0 : (j1 > 62 ? 62 : j1);
                        float t0 = u0 - (float)j0, t1 = u1 - (float)j1;
                        float4 p0 = tab[il * 64 + j0];
                        float4 p1 = tab[(il + 1) * 64 + j1];
                        res0 = fmaf(fmaf(fmaf(p0.w, t0, p0.z), t0, p0.y), t0, p0.x);
                        res1 = fmaf(fmaf(fmaf(p1.w, t1, p1.z), t1, p1.y), t1, p1.x);
                        if (xv2.x < -1.0f || xv2.x >= 1.0f) res0 = 0.0f;
                        if (xv2.y < -1.0f || xv2.y >= 1.0f) res1 = 0.0f;
                    }
                    hw[hk * 2 + rr] = h2_as_u32(__floats2half2_rn(res0, res1));
                }
            }
            uint4 o;
            o.x = hw[0];   // row g,   k 2t,2t+1
            o.y = hw[1];   // row g+8, k 2t,2t+1
            o.z = hw[2];   // row g,   k 2t+8,2t+9
            o.w = hw[3];   // row g+8, k 2t+8,2t+9
            int mf = bb * 8 + mfl;
            int kf = sel ? (16 + ib) : ib;
            g_actH[((size_t)mf * 32 + kf) * 32 + lane] = o;
        }
    }
}

// ---------------------------------------------------------------------------
// GEMM: out[4096,512] = Act @ W, fp16 mma.sync m16n8k16, fp32 accum.
// CTA tile 128x128, BK=64, grid (4, 32) = 128 CTAs, single wave, 512 threads:
// 16 warps (4m x 4n), warp tile 32x32 -> 4 warps/SMSP for latency hiding.
// 4-stage cp.async, 32KB/stage (128KB), fully unrolled, exact tail waits.
// ---------------------------------------------------------------------------
#define NITER 8
#define STAGES 4
#define STAGE_BYTES 32768   // A 16KB + B 16KB

__device__ __forceinline__ void cp_async16(uint32_t dst, const void* src) {
    asm volatile("cp.async.cg.shared.global [%0], [%1], 16;\n"
                 :: "r"(dst), "l"(src));
}
template <int N>
__device__ __forceinline__ void cp_wait() {
    asm volatile("cp.async.wait_group %0;" :: "n"(N));
}

__global__ __launch_bounds__(512) void kan_gemm_kernel(float* __restrict__ out) {
    extern __shared__ unsigned char sm[];

    const int tid  = threadIdx.x;
    const int lane = tid & 31;
    const int wid  = tid >> 5;
    const int wm   = wid & 3;   // 4 warp rows (32 each)
    const int wn   = wid >> 2;  // 4 warp cols (32 each)
    const int g    = lane >> 2;
    const int t    = lane & 3;
    const int bm   = blockIdx.y * 128;
    const int bn   = blockIdx.x * 128;

    const uint32_t sm_u = (uint32_t)__cvta_generic_to_shared(sm);

    // copy plan per iter: A = 1024 uint4 (2/thread), B = 1024 uint4 (2/thread)
    const int mf0 = bm >> 4;
    const int nf0 = bn >> 3;
    uint32_t aGidx[2], bGidx[2];
#pragma unroll
    for (int q = 0; q < 2; ++q) {
        int id = tid + 512 * q;                      // 0..1023
        int mfl = id >> 7, kflA = (id >> 5) & 3, ln = id & 31;
        aGidx[q] = (uint32_t)(((mf0 + mfl) * 32 + kflA) * 32 + ln);
        int kflB = id >> 8, rem = id & 255;          // rem = nfl*16 + pair
        bGidx[q] = (uint32_t)((kflB * 64 + nf0 + (rem >> 4)) * 16 + (rem & 15));
    }

    const uint4* gA = (const uint4*)g_actH;
    const uint4* gB = (const uint4*)g_wpH;

    auto issue = [&](int it) {
        uint32_t base = sm_u + (uint32_t)(it % STAGES) * STAGE_BYTES;
#pragma unroll
        for (int q = 0; q < 2; ++q) {
            int id = tid + 512 * q;
            cp_async16(base + id * 16,         gA + aGidx[q] + it * 128);
            cp_async16(base + 16384 + id * 16, gB + bGidx[q] + it * 4096);
        }
        asm volatile("cp.async.commit_group;");
    };

    issue(0);
    issue(1);
    issue(2);

    float acc[2][4][4];
#pragma unroll
    for (int mt = 0; mt < 2; ++mt)
#pragma unroll
        for (int nt = 0; nt < 4; ++nt)
#pragma unroll
            for (int e = 0; e < 4; ++e) acc[mt][nt][e] = 0.0f;

#pragma unroll
    for (int it = 0; it < NITER; ++it) {
        // exact wait: group `it` must be complete
        if      (it < NITER - 2)  cp_wait<2>();
        else if (it == NITER - 2) cp_wait<1>();
        else                      cp_wait<0>();
        __syncthreads();
        if (it + 3 < NITER) issue(it + 3);

        const uint4* As = (const uint4*)(sm + (it % STAGES) * STAGE_BYTES);
        const uint2* Bs = (const uint2*)(sm + (it % STAGES) * STAGE_BYTES + 16384);

#pragma unroll
        for (int kfl = 0; kfl < 4; ++kfl) {
            uint4 a[2];
#pragma unroll
            for (int mt = 0; mt < 2; ++mt)
                a[mt] = As[((wm * 2 + mt) * 4 + kfl) * 32 + lane];
            uint2 b[4];
#pragma unroll
            for (int nt = 0; nt < 4; ++nt)
                b[nt] = Bs[(kfl * 16 + wn * 4 + nt) * 32 + lane];
#pragma unroll
            for (int nt = 0; nt < 4; ++nt) {
#pragma unroll
                for (int mt = 0; mt < 2; ++mt) {
                    asm volatile(
                        "mma.sync.aligned.m16n8k16.row.col.f32.f16.f16.f32 "
                        "{%0,%1,%2,%3}, {%4,%5,%6,%7}, {%8,%9}, {%0,%1,%2,%3};"
                        : "+f"(acc[mt][nt][0]), "+f"(acc[mt][nt][1]),
                          "+f"(acc[mt][nt][2]), "+f"(acc[mt][nt][3])
                        : "r"(a[mt].x), "r"(a[mt].y), "r"(a[mt].z), "r"(a[mt].w),
                          "r"(b[nt].x), "r"(b[nt].y));
                }
            }
        }
    }

    // epilogue
#pragma unroll
    for (int mt = 0; mt < 2; ++mt) {
        int row = bm + wm * 32 + mt * 16 + g;
#pragma unroll
        for (int nt = 0; nt < 4; ++nt) {
            int col = bn + wn * 32 + nt * 8 + 2 * t;
            *(float2*)(out + (size_t)row * ODIM + col) =
                make_float2(acc[mt][nt][0], acc[mt][nt][1]);
            *(float2*)(out + (size_t)(row + 8) * ODIM + col) =
                make_float2(acc[mt][nt][2], acc[mt][nt][3]);
        }
    }
}

// ---------------------------------------------------------------------------
extern "C" void kernel_launch(void* const* d_in, const int* in_sizes, int n_in,
                              void* d_out, int out_size) {
    const float* x   = (const float*)d_in[0];
    const float* wb  = (const float*)d_in[1];
    const float* ws  = (const float*)d_in[2];
    const float* cps = (const float*)d_in[3];
    // d_in[4] = knots: uniform linspace(-1,1,64), folded into constants.
    float* out = (float*)d_out;

    cudaFuncSetAttribute(kan_gemm_kernel,
                         cudaFuncAttributeMaxDynamicSharedMemorySize,
                         STAGES * STAGE_BYTES);

    kan_prep_kernel<<<WPACK_BLOCKS + ACT_BLOCKS, 256>>>(x, cps, wb, ws);

    dim3 grid(ODIM / 128, BATCH / 128);   // (4, 32) = 128 CTAs
    kan_gemm_kernel<<<grid, 512, STAGES * STAGE_BYTES>>>(out);
}